// round 2
// baseline (speedup 1.0000x reference)
#include <cuda_runtime.h>

#define NE 8
#define NT 2048
#define ND 2048
#define NH 4096

// Scratch for the SwiGLU intermediate h = silu(x@w1) * (x@w3): E*T*H fp32 = 256 MiB.
// __device__ global (no allocation in kernel_launch, per harness rules).
__device__ float g_h[(long long)NE * NT * NH];

// ---------------------------------------------------------------------------
// GEMM1 (fused): for expert e:  g_h[t,h] = silu(x@w1)[t,h] * (x@w3)[t,h]
// Tiles: BM=128, BN=64, BK=16. 256 threads, each computes 8x4 for BOTH B1 and B3
// accumulators (A tile shared between the two GEMMs).
// ---------------------------------------------------------------------------
__global__ __launch_bounds__(256, 2)
void gemm1_swiglu(const float* __restrict__ X,
                  const float* __restrict__ W1,
                  const float* __restrict__ W3)
{
    constexpr int BM = 128, BN = 64, BK = 16;
    __shared__ float As [BK][BM];   // A stored transposed: As[k][m]
    __shared__ float B1s[BK][BN];
    __shared__ float B3s[BK][BN];

    const int e = blockIdx.z;
    const float* A  = X  + (long long)e * NT * ND;
    const float* B1 = W1 + (long long)e * ND * NH;
    const float* B3 = W3 + (long long)e * ND * NH;
    float* C = g_h + (long long)e * NT * NH;

    const int row0 = blockIdx.y * BM;   // token rows
    const int col0 = blockIdx.x * BN;   // hidden cols
    const int tid  = threadIdx.x;

    // compute mapping: ty -> 8 rows, tx -> 4 cols
    const int ty = tid >> 4;            // 0..15
    const int tx = tid & 15;            // 0..15

    // A-load mapping: 128x16 tile = 512 float4; 2 per thread
    const int aRow = tid >> 2;          // 0..63  (and +64)
    const int aCol = (tid & 3) << 2;    // 0,4,8,12
    // B-load mapping: 16x64 tile = 256 float4; 1 per thread (per matrix)
    const int bRow = tid >> 4;          // 0..15
    const int bCol = (tid & 15) << 2;   // 0..60

    float acc1[8][4];
    float acc3[8][4];
    #pragma unroll
    for (int i = 0; i < 8; ++i)
        #pragma unroll
        for (int j = 0; j < 4; ++j) { acc1[i][j] = 0.f; acc3[i][j] = 0.f; }

    for (int k0 = 0; k0 < ND; k0 += BK) {
        // --- load A tile (transposed into SMEM) ---
        #pragma unroll
        for (int r = 0; r < 2; ++r) {
            const int row = aRow + r * 64;
            float4 v = *(const float4*)&A[(long long)(row0 + row) * ND + k0 + aCol];
            As[aCol + 0][row] = v.x;
            As[aCol + 1][row] = v.y;
            As[aCol + 2][row] = v.z;
            As[aCol + 3][row] = v.w;
        }
        // --- load B1/B3 tiles ---
        {
            float4 v1 = *(const float4*)&B1[(long long)(k0 + bRow) * NH + col0 + bCol];
            *(float4*)&B1s[bRow][bCol] = v1;
            float4 v3 = *(const float4*)&B3[(long long)(k0 + bRow) * NH + col0 + bCol];
            *(float4*)&B3s[bRow][bCol] = v3;
        }
        __syncthreads();

        #pragma unroll
        for (int kk = 0; kk < BK; ++kk) {
            float a[8];
            #pragma unroll
            for (int i = 0; i < 8; ++i) a[i] = As[kk][ty * 8 + i];
            const float4 b1 = *(const float4*)&B1s[kk][tx * 4];
            const float4 b3 = *(const float4*)&B3s[kk][tx * 4];
            #pragma unroll
            for (int i = 0; i < 8; ++i) {
                acc1[i][0] += a[i] * b1.x;
                acc1[i][1] += a[i] * b1.y;
                acc1[i][2] += a[i] * b1.z;
                acc1[i][3] += a[i] * b1.w;
                acc3[i][0] += a[i] * b3.x;
                acc3[i][1] += a[i] * b3.y;
                acc3[i][2] += a[i] * b3.z;
                acc3[i][3] += a[i] * b3.w;
            }
        }
        __syncthreads();
    }

    // --- epilogue: silu(v1) * v3, vectorized store ---
    #pragma unroll
    for (int i = 0; i < 8; ++i) {
        float4 o;
        float* po = (float*)&o;
        #pragma unroll
        for (int j = 0; j < 4; ++j) {
            const float v1 = acc1[i][j];
            const float v3 = acc3[i][j];
            const float s  = v1 / (1.0f + __expf(-v1));  // silu
            po[j] = s * v3;
        }
        *(float4*)&C[(long long)(row0 + ty * 8 + i) * NH + col0 + tx * 4] = o;
    }
}

// ---------------------------------------------------------------------------
// GEMM2: out[t,d] = h @ w2.  Tiles: BM=128, BN=128, BK=16. 256 threads, 8x8
// microtile (cols split as tx*4 and 64+tx*4 for conflict-free SMEM reads).
// ---------------------------------------------------------------------------
__global__ __launch_bounds__(256, 2)
void gemm2_kernel(const float* __restrict__ W2, float* __restrict__ Out)
{
    constexpr int BM = 128, BN = 128, BK = 16;
    __shared__ float As[BK][BM];
    __shared__ float Bs[BK][BN];

    const int e = blockIdx.z;
    const float* A = g_h + (long long)e * NT * NH;
    const float* B = W2  + (long long)e * NH * ND;
    float* C = Out + (long long)e * NT * ND;

    const int row0 = blockIdx.y * BM;
    const int col0 = blockIdx.x * BN;
    const int tid  = threadIdx.x;

    const int ty = tid >> 4;            // 0..15 -> 8 rows
    const int tx = tid & 15;            // 0..15 -> cols tx*4 and 64+tx*4

    const int aRow = tid >> 2;          // 0..63 (and +64)
    const int aCol = (tid & 3) << 2;
    const int bRow = tid >> 5;          // 0..7 (and +8)
    const int bCol = (tid & 31) << 2;   // 0..124

    float acc[8][8];
    #pragma unroll
    for (int i = 0; i < 8; ++i)
        #pragma unroll
        for (int j = 0; j < 8; ++j) acc[i][j] = 0.f;

    for (int k0 = 0; k0 < NH; k0 += BK) {
        #pragma unroll
        for (int r = 0; r < 2; ++r) {
            const int row = aRow + r * 64;
            float4 v = *(const float4*)&A[(long long)(row0 + row) * NH + k0 + aCol];
            As[aCol + 0][row] = v.x;
            As[aCol + 1][row] = v.y;
            As[aCol + 2][row] = v.z;
            As[aCol + 3][row] = v.w;
        }
        #pragma unroll
        for (int r = 0; r < 2; ++r) {
            const int row = bRow + r * 8;
            float4 v = *(const float4*)&B[(long long)(k0 + row) * ND + col0 + bCol];
            *(float4*)&Bs[row][bCol] = v;
        }
        __syncthreads();

        #pragma unroll
        for (int kk = 0; kk < BK; ++kk) {
            float a[8];
            #pragma unroll
            for (int i = 0; i < 8; ++i) a[i] = As[kk][ty * 8 + i];
            const float4 bl = *(const float4*)&Bs[kk][tx * 4];
            const float4 bh = *(const float4*)&Bs[kk][64 + tx * 4];
            #pragma unroll
            for (int i = 0; i < 8; ++i) {
                acc[i][0] += a[i] * bl.x;
                acc[i][1] += a[i] * bl.y;
                acc[i][2] += a[i] * bl.z;
                acc[i][3] += a[i] * bl.w;
                acc[i][4] += a[i] * bh.x;
                acc[i][5] += a[i] * bh.y;
                acc[i][6] += a[i] * bh.z;
                acc[i][7] += a[i] * bh.w;
            }
        }
        __syncthreads();
    }

    #pragma unroll
    for (int i = 0; i < 8; ++i) {
        float4 o0, o1;
        o0.x = acc[i][0]; o0.y = acc[i][1]; o0.z = acc[i][2]; o0.w = acc[i][3];
        o1.x = acc[i][4]; o1.y = acc[i][5]; o1.z = acc[i][6]; o1.w = acc[i][7];
        const long long rbase = (long long)(row0 + ty * 8 + i) * ND + col0;
        *(float4*)&C[rbase + tx * 4]      = o0;
        *(float4*)&C[rbase + 64 + tx * 4] = o1;
    }
}

// ---------------------------------------------------------------------------
// Inputs (metadata order): x [E,T,D] fp32, w1 [E,D,H] fp32, w2 [E,H,D] fp32,
// w3 [E,D,H] fp32. Output: [E,T,D] fp32.
// ---------------------------------------------------------------------------
extern "C" void kernel_launch(void* const* d_in, const int* in_sizes, int n_in,
                              void* d_out, int out_size)
{
    const float* x  = (const float*)d_in[0];
    const float* w1 = (const float*)d_in[1];
    const float* w2 = (const float*)d_in[2];
    const float* w3 = (const float*)d_in[3];
    float* out = (float*)d_out;

    dim3 g1(NH / 64, NT / 128, NE);     // 64 x 16 x 8
    gemm1_swiglu<<<g1, 256>>>(x, w1, w3);

    dim3 g2(ND / 128, NT / 128, NE);    // 16 x 16 x 8
    gemm2_kernel<<<g2, 256>>>(w2, out);
}